// round 14
// baseline (speedup 1.0000x reference)
#include <cuda_runtime.h>
#include <cuda_fp16.h>
#include <cstdint>

// ---------------------------------------------------------------------------
// Problem dims
// ---------------------------------------------------------------------------
static constexpr int BATCH = 16;
static constexpr int LQ    = 2048;
static constexpr int LK    = 2048;
static constexpr int DIM   = 128;
static constexpr float SCALE_LOG2E = 0.08838834764831845f * 1.4426950408889634f;

static constexpr size_t NEL  = (size_t)BATCH * LQ * DIM;
static constexpr size_t NELE = (size_t)BATCH * LQ * LK;

// fp16 scratch (device globals = allowed scratch)
__device__ __half g_Qhi[NEL];
__device__ __half g_Khi[NEL];
__device__ __half g_Vhi[NEL];
__device__ __half g_E[NELE];          // unnormalized exp(S), fp16

// ---------------------------------------------------------------------------
// PTX helpers (sm_80-class only)
// ---------------------------------------------------------------------------
__device__ __forceinline__ uint32_t smem_u32(const void* p) {
    uint32_t a;
    asm("{ .reg .u64 t; cvta.to.shared.u64 t, %1; cvt.u32.u64 %0, t; }" : "=r"(a) : "l"(p));
    return a;
}
__device__ __forceinline__ float ex2(float x) {
    float r; asm("ex2.approx.f32 %0, %1;" : "=f"(r) : "f"(x)); return r;
}
__device__ __forceinline__ void ldsm4(uint32_t (&r)[4], uint32_t addr) {
    asm volatile("ldmatrix.sync.aligned.m8n8.x4.shared.b16 {%0,%1,%2,%3}, [%4];"
                 : "=r"(r[0]), "=r"(r[1]), "=r"(r[2]), "=r"(r[3]) : "r"(addr));
}
__device__ __forceinline__ void ldsm4t(uint32_t (&r)[4], uint32_t addr) {
    asm volatile("ldmatrix.sync.aligned.m8n8.x4.trans.shared.b16 {%0,%1,%2,%3}, [%4];"
                 : "=r"(r[0]), "=r"(r[1]), "=r"(r[2]), "=r"(r[3]) : "r"(addr));
}
__device__ __forceinline__ void mma16816(float (&d)[4], const uint32_t (&a)[4],
                                         uint32_t b0, uint32_t b1) {
    asm volatile(
        "mma.sync.aligned.m16n8k16.row.col.f32.f16.f16.f32 "
        "{%0,%1,%2,%3},{%4,%5,%6,%7},{%8,%9},{%0,%1,%2,%3};"
        : "+f"(d[0]), "+f"(d[1]), "+f"(d[2]), "+f"(d[3])
        : "r"(a[0]), "r"(a[1]), "r"(a[2]), "r"(a[3]), "r"(b0), "r"(b1));
}
__device__ __forceinline__ void cp16(uint32_t smem, const void* g) {
    asm volatile("cp.async.cg.shared.global [%0], [%1], 16;" :: "r"(smem), "l"(g) : "memory");
}
__device__ __forceinline__ void cp_commit() { asm volatile("cp.async.commit_group;" ::: "memory"); }
__device__ __forceinline__ void cp_wait0()  { asm volatile("cp.async.wait_group 0;" ::: "memory"); }
__device__ __forceinline__ void cp_wait2()  { asm volatile("cp.async.wait_group 2;" ::: "memory"); }

__device__ __forceinline__ uint32_t packh2(__half a, __half b) {
    __half2 p{a, b};
    return *reinterpret_cast<uint32_t*>(&p);
}

// ---------------------------------------------------------------------------
// Kernel 0: preconvert Q (scaled) / K / V -> fp16
// ---------------------------------------------------------------------------
__global__ __launch_bounds__(256) void preconvert_kernel(const float* __restrict__ Q,
                                                         const float* __restrict__ K,
                                                         const float* __restrict__ V) {
    const size_t t = (size_t)blockIdx.x * 256 + threadIdx.x;
    const int which = blockIdx.y;
    const float* src = (which == 0) ? Q : (which == 1) ? K : V;
    __half* dst = (which == 0) ? g_Qhi : (which == 1) ? g_Khi : g_Vhi;

    float4 v = reinterpret_cast<const float4*>(src)[t];
    if (which == 0) { v.x *= SCALE_LOG2E; v.y *= SCALE_LOG2E; v.z *= SCALE_LOG2E; v.w *= SCALE_LOG2E; }
    uint2 hh{packh2(__float2half_rn(v.x), __float2half_rn(v.y)),
             packh2(__float2half_rn(v.z), __float2half_rn(v.w))};
    reinterpret_cast<uint2*>(dst)[t] = hh;
}

// ---------------------------------------------------------------------------
// Fused attention kernel (pure fp16 QK/PV, fp32 accum + fp32 exp).
// CTA: 64 q-rows x full LK, 256 threads, 8 warps: wm = wid&3 (16 q-rows),
// wn = wid>>2 (16-wide k-slice of each 32-k chunk).
// K/V chunks: 4-stage cp.async ring with wait_group 2 (two chunks of slack).
// E stored fp16 to g_E (packed mma A-frags); tail converts to fp32 P.
// ---------------------------------------------------------------------------
static constexpr int RSB    = 272;                // padded row stride (bytes)
static constexpr int OFF_Q  = 0;
static constexpr int QT     = 64 * RSB;           // 17408
static constexpr int OFF_ST = QT;                 // 17408
static constexpr int KSZ    = 32 * RSB;           // 8704 (32 k-rows)
static constexpr int S_KHI = 0, S_VHI = KSZ;
static constexpr int STAGE  = 2 * KSZ;            // 17408
static constexpr int OFF_INV = OFF_ST + 4 * STAGE;  // 87040
static constexpr int SMEM_BYTES = OFF_INV + 1024;   // 88064

__global__ __launch_bounds__(256, 2) void fused_attn_kernel(float* __restrict__ P,
                                                            float* __restrict__ R) {
    extern __shared__ char sm[];
    const uint32_t sb = smem_u32(sm);

    const int tid = threadIdx.x, lane = tid & 31, wid = tid >> 5;
    const int wm = wid & 3, wn = wid >> 2;
    const int g = lane >> 2, c2 = (lane & 3) * 2;
    const int qt = blockIdx.x * 64, b = blockIdx.y;

    const size_t kvbase = (size_t)b * LK * DIM;

    // ---- stage Q (folded into group 0) ----
    {
        const size_t qbase = ((size_t)b * LQ + qt) * DIM;
#pragma unroll
        for (int it = 0; it < 4; ++it) {
            int i = tid + it * 256;               // 0..1023
            int row = i >> 4, chk = i & 15;
            uint32_t so = (uint32_t)(row * RSB + chk * 16);
            cp16(sb + OFF_Q + so, g_Qhi + qbase + (size_t)row * DIM + chk * 8);
        }
    }
    // ---- prologue: commit chunks 0,1,2 (3 groups; group 0 includes Q) ----
#pragma unroll
    for (int pc = 0; pc < 3; ++pc) {
        const uint32_t dst = sb + OFF_ST + (uint32_t)(pc * STAGE);
        const size_t kb = kvbase + (size_t)pc * 32 * DIM;
#pragma unroll
        for (int it = 0; it < 2; ++it) {
            int i = tid + it * 256;               // 0..511
            int row = i >> 4, chk = i & 15;
            uint32_t so = (uint32_t)(row * RSB + chk * 16);
            const size_t gg = kb + (size_t)row * DIM + chk * 8;
            cp16(dst + S_KHI + so, g_Khi + gg);
            cp16(dst + S_VHI + so, g_Vhi + gg);
        }
        cp_commit();
    }

    const uint32_t aoff  = (uint32_t)((lane & 15) * RSB + (lane >> 4) * 16);
    const uint32_t boff  = (uint32_t)(((lane & 7) + (lane >> 4) * 8) * RSB + ((lane >> 3) & 1) * 16);
    const uint32_t boffT = (uint32_t)(((lane & 7) + ((lane >> 3) & 1) * 8) * RSB + (lane >> 4) * 16);

    const uint32_t qaHi = sb + OFF_Q + (uint32_t)(wm * 16) * RSB + aoff;

    float racc[16][4];
#pragma unroll
    for (int j = 0; j < 16; ++j)
#pragma unroll
        for (int c = 0; c < 4; ++c) racc[j][c] = 0.f;
    float rs0 = 0.f, rs1 = 0.f;

    // E (fp16) row pointers: rows (qt+wm*16+g, +8), cols kc*32 + wn*16 + ...
    __half* E0 = g_E + ((size_t)b * LQ + qt + wm * 16 + g) * LK + wn * 16 + c2;
    __half* E1 = E0 + (size_t)8 * LK;

#pragma unroll 1
    for (int kc = 0; kc < 64; ++kc) {
        // chunk kc guaranteed arrived once <=2 groups remain outstanding
        if (kc >= 61) cp_wait0(); else cp_wait2();
        __syncthreads();

        // prefetch chunk kc+3 into ring slot (kc+3)&3 (read-complete since iter kc-1)
        if (kc < 61) {
            const uint32_t dst = sb + OFF_ST + (uint32_t)(((kc + 3) & 3) * STAGE);
            const size_t kb = kvbase + (size_t)(kc + 3) * 32 * DIM;
#pragma unroll
            for (int it = 0; it < 2; ++it) {
                int i = tid + it * 256;
                int row = i >> 4, chk = i & 15;
                uint32_t so = (uint32_t)(row * RSB + chk * 16);
                const size_t gg = kb + (size_t)row * DIM + chk * 8;
                cp16(dst + S_KHI + so, g_Khi + gg);
                cp16(dst + S_VHI + so, g_Vhi + gg);
            }
            cp_commit();
        }

        const uint32_t buf = sb + OFF_ST + (uint32_t)((kc & 3) * STAGE);

        // ---- QK: S[16q x 16k] per warp ----
        float s[2][4];
#pragma unroll
        for (int j = 0; j < 2; ++j)
#pragma unroll
            for (int c = 0; c < 4; ++c) s[j][c] = 0.f;

        const uint32_t kh = buf + S_KHI + (uint32_t)(wn * 16) * RSB + boff;
#pragma unroll
        for (int ks = 0; ks < 8; ++ks) {
            uint32_t qh[4], bh[4];
            ldsm4(qh, qaHi + ks * 32);
            ldsm4(bh, kh + ks * 32);
            mma16816(s[0], qh, bh[0], bh[1]);
            mma16816(s[1], qh, bh[2], bh[3]);
        }

        // ---- exp2, rowsums, pack fp16 A-frags ----
        float e[2][4];
#pragma unroll
        for (int j = 0; j < 2; ++j) {
            e[j][0] = ex2(s[j][0]); e[j][1] = ex2(s[j][1]);
            e[j][2] = ex2(s[j][2]); e[j][3] = ex2(s[j][3]);
            rs0 += e[j][0] + e[j][1];
            rs1 += e[j][2] + e[j][3];
        }
        uint32_t sh[4];
#pragma unroll
        for (int j = 0; j < 2; ++j) {
            sh[j * 2 + 0] = packh2(__float2half_rn(e[j][0]), __float2half_rn(e[j][1]));
            sh[j * 2 + 1] = packh2(__float2half_rn(e[j][2]), __float2half_rn(e[j][3]));
        }

        // ---- PV: racc += Sh * Vhi over this warp's 16-k slice ----
        const uint32_t vb = buf + S_VHI + (uint32_t)(wn * 16) * RSB + boffT;
#pragma unroll
        for (int nb = 0; nb < 8; ++nb) {
            uint32_t bv[4];
            ldsm4t(bv, vb + nb * 32);
            mma16816(racc[nb * 2],     sh, bv[0], bv[1]);
            mma16816(racc[nb * 2 + 1], sh, bv[2], bv[3]);
        }

        // ---- store E fp16 (already packed) ----
        *reinterpret_cast<uint32_t*>(E0 + kc * 32)     = sh[0];
        *reinterpret_cast<uint32_t*>(E1 + kc * 32)     = sh[1];
        *reinterpret_cast<uint32_t*>(E0 + kc * 32 + 8) = sh[2];
        *reinterpret_cast<uint32_t*>(E1 + kc * 32 + 8) = sh[3];
    }

    // ---- cross-warp combine (wn pairs), rowsums, R store ----
    rs0 += __shfl_xor_sync(0xFFFFFFFFu, rs0, 1);
    rs0 += __shfl_xor_sync(0xFFFFFFFFu, rs0, 2);
    rs1 += __shfl_xor_sync(0xFFFFFFFFu, rs1, 1);
    rs1 += __shfl_xor_sync(0xFFFFFFFFu, rs1, 2);

    float* partial = reinterpret_cast<float*>(sm + OFF_INV);
    float* inv     = reinterpret_cast<float*>(sm + OFF_INV + 256);

    __syncthreads();

    if (wn == 1) {
        float4* red = reinterpret_cast<float4*>(sm + wm * 8192);
#pragma unroll
        for (int j = 0; j < 16; ++j)
            red[j * 32 + lane] = *reinterpret_cast<float4*>(racc[j]);
        if ((lane & 3) == 0) {
            partial[wm * 16 + g]     = rs0;
            partial[wm * 16 + 8 + g] = rs1;
        }
    }
    __syncthreads();

    if (wn == 0) {
        const float4* red = reinterpret_cast<const float4*>(sm + wm * 8192);
#pragma unroll
        for (int j = 0; j < 16; ++j) {
            float4 o = red[j * 32 + lane];
            racc[j][0] += o.x; racc[j][1] += o.y; racc[j][2] += o.z; racc[j][3] += o.w;
        }
        const int row0 = wm * 16 + g, row1 = row0 + 8;
        const float iv0 = 1.f / (rs0 + partial[row0]);
        const float iv1 = 1.f / (rs1 + partial[row1]);
        if ((lane & 3) == 0) { inv[row0] = iv0; inv[row1] = iv1; }

        float* Rp = R + ((size_t)b * LQ + qt + row0) * DIM + c2;
#pragma unroll
        for (int j = 0; j < 16; ++j) {
            float2 v0{racc[j][0] * iv0, racc[j][1] * iv0};
            float2 v1{racc[j][2] * iv1, racc[j][3] * iv1};
            *reinterpret_cast<float2*>(Rp + j * 8)           = v0;
            *reinterpret_cast<float2*>(Rp + 8 * DIM + j * 8) = v1;
        }
    }
    __syncthreads();

    // ---- tail: P = fp16 E * inv (read 128B-contig fp16, write fp32) ----
    const __half* Es = g_E + ((size_t)b * LQ + qt) * LK;
    float* Pt = P + ((size_t)b * LQ + qt) * LK;
#pragma unroll 4
    for (int it = 0; it < 64; ++it) {
        int idx = tid + it * 256;          // 0..16383 uint4 slots (8 halves each)
        int r = idx >> 8, c8 = idx & 255;
        const uint4 hv = *reinterpret_cast<const uint4*>(Es + (size_t)r * LK + c8 * 8);
        const float iv = inv[r];
        const __half2* hp = reinterpret_cast<const __half2*>(&hv);
        float2 f0 = __half22float2(hp[0]), f1 = __half22float2(hp[1]);
        float2 f2 = __half22float2(hp[2]), f3 = __half22float2(hp[3]);
        float4 o0{f0.x * iv, f0.y * iv, f1.x * iv, f1.y * iv};
        float4 o1{f2.x * iv, f2.y * iv, f3.x * iv, f3.y * iv};
        float* pd = Pt + (size_t)r * LK + c8 * 8;
        *reinterpret_cast<float4*>(pd)     = o0;
        *reinterpret_cast<float4*>(pd + 4) = o1;
    }
}

// ---------------------------------------------------------------------------
// Launch: d_out = [ R | P ]
// ---------------------------------------------------------------------------
extern "C" void kernel_launch(void* const* d_in, const int* in_sizes, int n_in,
                              void* d_out, int out_size) {
    const float* Q = (const float*)d_in[0];
    const float* K = (const float*)d_in[1];
    const float* V = (const float*)d_in[2];
    float* R = (float*)d_out;
    float* P = (float*)d_out + (size_t)BATCH * LQ * DIM;

    cudaFuncSetAttribute(fused_attn_kernel, cudaFuncAttributeMaxDynamicSharedMemorySize, SMEM_BYTES);

    {
        dim3 grid((unsigned)(NEL / 4 / 256), 3);
        preconvert_kernel<<<grid, 256>>>(Q, K, V);
    }
    {
        dim3 grid(LQ / 64, BATCH);
        fused_attn_kernel<<<grid, 256, SMEM_BYTES>>>(P, R);
    }
}

// round 15
// speedup vs baseline: 1.1137x; 1.1137x over previous
#include <cuda_runtime.h>
#include <cuda_fp16.h>
#include <cstdint>

// ---------------------------------------------------------------------------
// Problem dims
// ---------------------------------------------------------------------------
static constexpr int BATCH = 16;
static constexpr int LQ    = 2048;
static constexpr int LK    = 2048;
static constexpr int DIM   = 128;
static constexpr float SCALE_LOG2E = 0.08838834764831845f * 1.4426950408889634f;

static constexpr size_t NEL  = (size_t)BATCH * LQ * DIM;
static constexpr size_t NELE = (size_t)BATCH * LQ * LK;

// fp16 scratch (device globals = allowed scratch)
__device__ __half g_Khi[NEL];
__device__ __half g_Vhi[NEL];
__device__ __half g_E[NELE];          // unnormalized exp(S), fp16

// ---------------------------------------------------------------------------
// PTX helpers (sm_80-class only)
// ---------------------------------------------------------------------------
__device__ __forceinline__ uint32_t smem_u32(const void* p) {
    uint32_t a;
    asm("{ .reg .u64 t; cvta.to.shared.u64 t, %1; cvt.u32.u64 %0, t; }" : "=r"(a) : "l"(p));
    return a;
}
__device__ __forceinline__ float ex2(float x) {
    float r; asm("ex2.approx.f32 %0, %1;" : "=f"(r) : "f"(x)); return r;
}
__device__ __forceinline__ void ldsm4(uint32_t (&r)[4], uint32_t addr) {
    asm volatile("ldmatrix.sync.aligned.m8n8.x4.shared.b16 {%0,%1,%2,%3}, [%4];"
                 : "=r"(r[0]), "=r"(r[1]), "=r"(r[2]), "=r"(r[3]) : "r"(addr));
}
__device__ __forceinline__ void ldsm4t(uint32_t (&r)[4], uint32_t addr) {
    asm volatile("ldmatrix.sync.aligned.m8n8.x4.trans.shared.b16 {%0,%1,%2,%3}, [%4];"
                 : "=r"(r[0]), "=r"(r[1]), "=r"(r[2]), "=r"(r[3]) : "r"(addr));
}
__device__ __forceinline__ void mma16816(float (&d)[4], const uint32_t (&a)[4],
                                         uint32_t b0, uint32_t b1) {
    asm volatile(
        "mma.sync.aligned.m16n8k16.row.col.f32.f16.f16.f32 "
        "{%0,%1,%2,%3},{%4,%5,%6,%7},{%8,%9},{%0,%1,%2,%3};"
        : "+f"(d[0]), "+f"(d[1]), "+f"(d[2]), "+f"(d[3])
        : "r"(a[0]), "r"(a[1]), "r"(a[2]), "r"(a[3]), "r"(b0), "r"(b1));
}
__device__ __forceinline__ void cp16(uint32_t smem, const void* g) {
    asm volatile("cp.async.cg.shared.global [%0], [%1], 16;" :: "r"(smem), "l"(g) : "memory");
}
__device__ __forceinline__ void cp_commit() { asm volatile("cp.async.commit_group;" ::: "memory"); }
__device__ __forceinline__ void cp_wait0()  { asm volatile("cp.async.wait_group 0;" ::: "memory"); }
__device__ __forceinline__ void barg(int id) {   // named barrier, 128 threads
    asm volatile("bar.sync %0, 128;" :: "r"(id) : "memory");
}

__device__ __forceinline__ uint32_t packh2(__half a, __half b) {
    __half2 p{a, b};
    return *reinterpret_cast<uint32_t*>(&p);
}

// ---------------------------------------------------------------------------
// Kernel 0: preconvert K / V -> fp16 (Q handled inside fused kernel)
// ---------------------------------------------------------------------------
__global__ __launch_bounds__(256) void preconvert_kernel(const float* __restrict__ K,
                                                         const float* __restrict__ V) {
    const size_t t = (size_t)blockIdx.x * 256 + threadIdx.x;
    const int which = blockIdx.y;
    const float* src = (which == 0) ? K : V;
    __half* dst = (which == 0) ? g_Khi : g_Vhi;

    float4 v = reinterpret_cast<const float4*>(src)[t];
    uint2 hh{packh2(__float2half_rn(v.x), __float2half_rn(v.y)),
             packh2(__float2half_rn(v.z), __float2half_rn(v.w))};
    reinterpret_cast<uint2*>(dst)[t] = hh;
}

// ---------------------------------------------------------------------------
// Fused attention kernel (pure fp16 QK/PV, fp32 accum + fp32 exp).
// CTA: 64 q-rows x full LK, 256 threads, 8 warps as TWO INDEPENDENT GROUPS:
//   group wn = wid>>2 (warps 4wn..4wn+3, threads [128wn,128wn+128)).
//   Group wn owns the 32-k blocks with (block index & 1) == wn.
//   Each group: private double-buffered K/V slice staging + named barrier.
// Q converted fp32->fp16 in-kernel (resident in smem).
// E stored fp16 to g_E; tail converts to fp32 P.
// ---------------------------------------------------------------------------
static constexpr int RSB    = 272;                  // padded row stride (bytes)
static constexpr int OFF_Q  = 0;
static constexpr int QT     = 64 * RSB;             // 17408
static constexpr int OFF_ST = QT;                   // 17408
static constexpr int KSZ    = 32 * RSB;             // 8704 (32 k-rows)
static constexpr int S_KHI = 0, S_VHI = KSZ;
static constexpr int GSTAGE = 2 * KSZ;              // 17408 per stage (K+V)
static constexpr int GBUF   = 2 * GSTAGE;           // 34816 per group
static constexpr int OFF_INV = OFF_ST + 2 * GBUF;   // 87040
static constexpr int SMEM_BYTES = OFF_INV + 1024;   // 88064

__global__ __launch_bounds__(256, 2) void fused_attn_kernel(const float* __restrict__ Qf,
                                                            float* __restrict__ P,
                                                            float* __restrict__ R) {
    extern __shared__ char sm[];
    const uint32_t sb = smem_u32(sm);

    const int tid = threadIdx.x, lane = tid & 31, wid = tid >> 5;
    const int wm = wid & 3, wn = wid >> 2;
    const int gtid = tid & 127;                 // thread id within group
    const int g = lane >> 2, c2 = (lane & 3) * 2;
    const int qt = blockIdx.x * 64, b = blockIdx.y;

    const size_t kvbase = (size_t)b * LK * DIM;
    const uint32_t gbase = sb + OFF_ST + (uint32_t)(wn * GBUF);

    // ---- stage Q: load fp32, scale, convert, STS (all 256 threads) ----
    {
        const float* Qb = Qf + ((size_t)b * LQ + qt) * DIM;
#pragma unroll
        for (int it = 0; it < 8; ++it) {
            int i = tid + it * 256;                 // 0..2047 float4
            int row = i >> 5, col4 = (i & 31) * 4;
            float4 v = *reinterpret_cast<const float4*>(Qb + (size_t)row * DIM + col4);
            v.x *= SCALE_LOG2E; v.y *= SCALE_LOG2E; v.z *= SCALE_LOG2E; v.w *= SCALE_LOG2E;
            uint2 hh{packh2(__float2half_rn(v.x), __float2half_rn(v.y)),
                     packh2(__float2half_rn(v.z), __float2half_rn(v.w))};
            *reinterpret_cast<uint2*>(sm + OFF_Q + row * RSB + col4 * 2) = hh;
        }
    }
    // ---- stage chunk 0 for this group (k block index: 0*2 + wn) ----
    {
        const size_t kb = kvbase + (size_t)(wn * 32) * DIM;
#pragma unroll
        for (int it = 0; it < 4; ++it) {
            int i = gtid + it * 128;                // 0..511
            int row = i >> 4, chk = i & 15;
            uint32_t so = (uint32_t)(row * RSB + chk * 16);
            const size_t gg = kb + (size_t)row * DIM + chk * 8;
            cp16(gbase + S_KHI + so, g_Khi + gg);
            cp16(gbase + S_VHI + so, g_Vhi + gg);
        }
        cp_commit(); cp_wait0();
    }
    __syncthreads();   // Q visible to all + chunk 0 staged

    const uint32_t aoff  = (uint32_t)((lane & 15) * RSB + (lane >> 4) * 16);
    const uint32_t boff  = (uint32_t)(((lane & 7) + (lane >> 4) * 8) * RSB + ((lane >> 3) & 1) * 16);
    const uint32_t boffT = (uint32_t)(((lane & 7) + ((lane >> 3) & 1) * 8) * RSB + (lane >> 4) * 16);

    const uint32_t qaHi = sb + OFF_Q + (uint32_t)(wm * 16) * RSB + aoff;

    float racc[16][4];
#pragma unroll
    for (int j = 0; j < 16; ++j)
#pragma unroll
        for (int c = 0; c < 4; ++c) racc[j][c] = 0.f;
    float rs0 = 0.f, rs1 = 0.f;

    // E (fp16) row pointers: rows (qt+wm*16+g, +8); group's cols = kc*64 + wn*32
    __half* E0 = g_E + ((size_t)b * LQ + qt + wm * 16 + g) * LK + wn * 32 + c2;
    __half* E1 = E0 + (size_t)8 * LK;

#pragma unroll 1
    for (int kc = 0; kc < 32; ++kc) {
        // prefetch this group's next slice (k block 2*(kc+1)+wn)
        if (kc < 31) {
            const uint32_t dst = gbase + (uint32_t)(((kc + 1) & 1) * GSTAGE);
            const size_t kb = kvbase + (size_t)((kc + 1) * 64 + wn * 32) * DIM;
#pragma unroll
            for (int it = 0; it < 4; ++it) {
                int i = gtid + it * 128;
                int row = i >> 4, chk = i & 15;
                uint32_t so = (uint32_t)(row * RSB + chk * 16);
                const size_t gg = kb + (size_t)row * DIM + chk * 8;
                cp16(dst + S_KHI + so, g_Khi + gg);
                cp16(dst + S_VHI + so, g_Vhi + gg);
            }
            cp_commit();
        }

        const uint32_t buf = gbase + (uint32_t)((kc & 1) * GSTAGE);

        // ---- QK: warp computes S[16q x 32k] (group's slice), two 16-k halves ----
        float s0[2][4], s1[2][4];
#pragma unroll
        for (int j = 0; j < 2; ++j)
#pragma unroll
            for (int c = 0; c < 4; ++c) { s0[j][c] = 0.f; s1[j][c] = 0.f; }

        const uint32_t kh = buf + S_KHI + boff;
#pragma unroll
        for (int ks = 0; ks < 8; ++ks) {
            uint32_t qh[4], bh0[4], bh1[4];
            ldsm4(qh,  qaHi + ks * 32);
            ldsm4(bh0, kh + ks * 32);
            ldsm4(bh1, kh + 16 * RSB + ks * 32);
            mma16816(s0[0], qh, bh0[0], bh0[1]);
            mma16816(s0[1], qh, bh0[2], bh0[3]);
            mma16816(s1[0], qh, bh1[0], bh1[1]);
            mma16816(s1[1], qh, bh1[2], bh1[3]);
        }

        // ---- exp2 (32 values), rowsums, pack fp16 A-frags ----
        float e0[2][4], e1[2][4];
#pragma unroll
        for (int j = 0; j < 2; ++j) {
            e0[j][0] = ex2(s0[j][0]); e0[j][1] = ex2(s0[j][1]);
            e0[j][2] = ex2(s0[j][2]); e0[j][3] = ex2(s0[j][3]);
            e1[j][0] = ex2(s1[j][0]); e1[j][1] = ex2(s1[j][1]);
            e1[j][2] = ex2(s1[j][2]); e1[j][3] = ex2(s1[j][3]);
            rs0 += e0[j][0] + e0[j][1] + e1[j][0] + e1[j][1];
            rs1 += e0[j][2] + e0[j][3] + e1[j][2] + e1[j][3];
        }
        uint32_t sh0[4], sh1[4];
#pragma unroll
        for (int j = 0; j < 2; ++j) {
            sh0[j * 2 + 0] = packh2(__float2half_rn(e0[j][0]), __float2half_rn(e0[j][1]));
            sh0[j * 2 + 1] = packh2(__float2half_rn(e0[j][2]), __float2half_rn(e0[j][3]));
            sh1[j * 2 + 0] = packh2(__float2half_rn(e1[j][0]), __float2half_rn(e1[j][1]));
            sh1[j * 2 + 1] = packh2(__float2half_rn(e1[j][2]), __float2half_rn(e1[j][3]));
        }

        // ---- PV: racc += Sh0 * V(half0) + Sh1 * V(half1) ----
        const uint32_t vb = buf + S_VHI + boffT;
#pragma unroll
        for (int nb = 0; nb < 8; ++nb) {
            uint32_t bv[4];
            ldsm4t(bv, vb + nb * 32);
            mma16816(racc[nb * 2],     sh0, bv[0], bv[1]);
            mma16816(racc[nb * 2 + 1], sh0, bv[2], bv[3]);
        }
#pragma unroll
        for (int nb = 0; nb < 8; ++nb) {
            uint32_t bv[4];
            ldsm4t(bv, vb + 16 * RSB + nb * 32);
            mma16816(racc[nb * 2],     sh1, bv[0], bv[1]);
            mma16816(racc[nb * 2 + 1], sh1, bv[2], bv[3]);
        }

        // ---- store E fp16 (already packed); group cols kc*64 + wn*32 ----
        *reinterpret_cast<uint32_t*>(E0 + kc * 64)      = sh0[0];
        *reinterpret_cast<uint32_t*>(E1 + kc * 64)      = sh0[1];
        *reinterpret_cast<uint32_t*>(E0 + kc * 64 + 8)  = sh0[2];
        *reinterpret_cast<uint32_t*>(E1 + kc * 64 + 8)  = sh0[3];
        *reinterpret_cast<uint32_t*>(E0 + kc * 64 + 16) = sh1[0];
        *reinterpret_cast<uint32_t*>(E1 + kc * 64 + 16) = sh1[1];
        *reinterpret_cast<uint32_t*>(E0 + kc * 64 + 24) = sh1[2];
        *reinterpret_cast<uint32_t*>(E1 + kc * 64 + 24) = sh1[3];

        // group-local: wait own prefetch, sync only this group's 4 warps
        cp_wait0();
        barg(wn + 1);
    }

    // ---- cross-warp combine (wn pairs), rowsums, R store ----
    rs0 += __shfl_xor_sync(0xFFFFFFFFu, rs0, 1);
    rs0 += __shfl_xor_sync(0xFFFFFFFFu, rs0, 2);
    rs1 += __shfl_xor_sync(0xFFFFFFFFu, rs1, 1);
    rs1 += __shfl_xor_sync(0xFFFFFFFFu, rs1, 2);

    float* partial = reinterpret_cast<float*>(sm + OFF_INV);
    float* inv     = reinterpret_cast<float*>(sm + OFF_INV + 256);

    __syncthreads();

    if (wn == 1) {
        float4* red = reinterpret_cast<float4*>(sm + wm * 8192);
#pragma unroll
        for (int j = 0; j < 16; ++j)
            red[j * 32 + lane] = *reinterpret_cast<float4*>(racc[j]);
        if ((lane & 3) == 0) {
            partial[wm * 16 + g]     = rs0;
            partial[wm * 16 + 8 + g] = rs1;
        }
    }
    __syncthreads();

    if (wn == 0) {
        const float4* red = reinterpret_cast<const float4*>(sm + wm * 8192);
#pragma unroll
        for (int j = 0; j < 16; ++j) {
            float4 o = red[j * 32 + lane];
            racc[j][0] += o.x; racc[j][1] += o.y; racc[j][2] += o.z; racc[j][3] += o.w;
        }
        const int row0 = wm * 16 + g, row1 = row0 + 8;
        const float iv0 = 1.f / (rs0 + partial[row0]);
        const float iv1 = 1.f / (rs1 + partial[row1]);
        if ((lane & 3) == 0) { inv[row0] = iv0; inv[row1] = iv1; }

        float* Rp = R + ((size_t)b * LQ + qt + row0) * DIM + c2;
#pragma unroll
        for (int j = 0; j < 16; ++j) {
            float2 v0{racc[j][0] * iv0, racc[j][1] * iv0};
            float2 v1{racc[j][2] * iv1, racc[j][3] * iv1};
            *reinterpret_cast<float2*>(Rp + j * 8)           = v0;
            *reinterpret_cast<float2*>(Rp + 8 * DIM + j * 8) = v1;
        }
    }
    __syncthreads();

    // ---- tail: P = fp16 E * inv (read 128B-contig fp16, write fp32) ----
    const __half* Es = g_E + ((size_t)b * LQ + qt) * LK;
    float* Pt = P + ((size_t)b * LQ + qt) * LK;
#pragma unroll 4
    for (int it = 0; it < 64; ++it) {
        int idx = tid + it * 256;          // 0..16383 uint4 slots (8 halves each)
        int r = idx >> 8, c8 = idx & 255;
        const uint4 hv = *reinterpret_cast<const uint4*>(Es + (size_t)r * LK + c8 * 8);
        const float iv = inv[r];
        const __half2* hp = reinterpret_cast<const __half2*>(&hv);
        float2 f0 = __half22float2(hp[0]), f1 = __half22float2(hp[1]);
        float2 f2 = __half22float2(hp[2]), f3 = __half22float2(hp[3]);
        float4 o0{f0.x * iv, f0.y * iv, f1.x * iv, f1.y * iv};
        float4 o1{f2.x * iv, f2.y * iv, f3.x * iv, f3.y * iv};
        float* pd = Pt + (size_t)r * LK + c8 * 8;
        *reinterpret_cast<float4*>(pd)     = o0;
        *reinterpret_cast<float4*>(pd + 4) = o1;
    }
}

// ---------------------------------------------------------------------------
// Launch: d_out = [ R | P ]
// ---------------------------------------------------------------------------
extern "C" void kernel_launch(void* const* d_in, const int* in_sizes, int n_in,
                              void* d_out, int out_size) {
    const float* Q = (const float*)d_in[0];
    const float* K = (const float*)d_in[1];
    const float* V = (const float*)d_in[2];
    float* R = (float*)d_out;
    float* P = (float*)d_out + (size_t)BATCH * LQ * DIM;

    cudaFuncSetAttribute(fused_attn_kernel, cudaFuncAttributeMaxDynamicSharedMemorySize, SMEM_BYTES);

    {
        dim3 grid((unsigned)(NEL / 4 / 256), 2);
        preconvert_kernel<<<grid, 256>>>(K, V);
    }
    {
        dim3 grid(LQ / 64, BATCH);
        fused_attn_kernel<<<grid, 256, SMEM_BYTES>>>(Q, P, R);
    }
}

// round 16
// speedup vs baseline: 1.1618x; 1.0432x over previous
#include <cuda_runtime.h>
#include <cuda_fp16.h>
#include <cstdint>

// ---------------------------------------------------------------------------
// Problem dims
// ---------------------------------------------------------------------------
static constexpr int BATCH = 16;
static constexpr int LQ    = 2048;
static constexpr int LK    = 2048;
static constexpr int DIM   = 128;
static constexpr float SCALE_LOG2E = 0.08838834764831845f * 1.4426950408889634f;

static constexpr size_t NEL  = (size_t)BATCH * LQ * DIM;
static constexpr size_t NELE = (size_t)BATCH * LQ * LK;

// fp16 scratch (device globals = allowed scratch)
__device__ __half g_Khi[NEL];
__device__ __half g_Vhi[NEL];
__device__ __half g_E[NELE];          // unnormalized exp(S), fp16

// ---------------------------------------------------------------------------
// PTX helpers (sm_80-class only)
// ---------------------------------------------------------------------------
__device__ __forceinline__ uint32_t smem_u32(const void* p) {
    uint32_t a;
    asm("{ .reg .u64 t; cvta.to.shared.u64 t, %1; cvt.u32.u64 %0, t; }" : "=r"(a) : "l"(p));
    return a;
}
__device__ __forceinline__ float ex2(float x) {
    float r; asm("ex2.approx.f32 %0, %1;" : "=f"(r) : "f"(x)); return r;
}
__device__ __forceinline__ void ldsm4(uint32_t (&r)[4], uint32_t addr) {
    asm volatile("ldmatrix.sync.aligned.m8n8.x4.shared.b16 {%0,%1,%2,%3}, [%4];"
                 : "=r"(r[0]), "=r"(r[1]), "=r"(r[2]), "=r"(r[3]) : "r"(addr));
}
__device__ __forceinline__ void ldsm4t(uint32_t (&r)[4], uint32_t addr) {
    asm volatile("ldmatrix.sync.aligned.m8n8.x4.trans.shared.b16 {%0,%1,%2,%3}, [%4];"
                 : "=r"(r[0]), "=r"(r[1]), "=r"(r[2]), "=r"(r[3]) : "r"(addr));
}
__device__ __forceinline__ void mma16816(float (&d)[4], const uint32_t (&a)[4],
                                         uint32_t b0, uint32_t b1) {
    asm volatile(
        "mma.sync.aligned.m16n8k16.row.col.f32.f16.f16.f32 "
        "{%0,%1,%2,%3},{%4,%5,%6,%7},{%8,%9},{%0,%1,%2,%3};"
        : "+f"(d[0]), "+f"(d[1]), "+f"(d[2]), "+f"(d[3])
        : "r"(a[0]), "r"(a[1]), "r"(a[2]), "r"(a[3]), "r"(b0), "r"(b1));
}
__device__ __forceinline__ void cp16(uint32_t smem, const void* g) {
    asm volatile("cp.async.cg.shared.global [%0], [%1], 16;" :: "r"(smem), "l"(g) : "memory");
}
__device__ __forceinline__ void cp_commit() { asm volatile("cp.async.commit_group;" ::: "memory"); }
__device__ __forceinline__ void cp_wait0()  { asm volatile("cp.async.wait_group 0;" ::: "memory"); }
__device__ __forceinline__ void barg(int id) {   // named barrier, 128 threads
    asm volatile("bar.sync %0, 128;" :: "r"(id) : "memory");
}

__device__ __forceinline__ uint32_t packh2(__half a, __half b) {
    __half2 p{a, b};
    return *reinterpret_cast<uint32_t*>(&p);
}

// ---------------------------------------------------------------------------
// Kernel 0: preconvert K / V -> fp16 (Q handled inside fused kernel)
// ---------------------------------------------------------------------------
__global__ __launch_bounds__(256) void preconvert_kernel(const float* __restrict__ K,
                                                         const float* __restrict__ V) {
    const size_t t = (size_t)blockIdx.x * 256 + threadIdx.x;
    const int which = blockIdx.y;
    const float* src = (which == 0) ? K : V;
    __half* dst = (which == 0) ? g_Khi : g_Vhi;

    float4 v = reinterpret_cast<const float4*>(src)[t];
    uint2 hh{packh2(__float2half_rn(v.x), __float2half_rn(v.y)),
             packh2(__float2half_rn(v.z), __float2half_rn(v.w))};
    reinterpret_cast<uint2*>(dst)[t] = hh;
}

// ---------------------------------------------------------------------------
// Fused attention kernel (pure fp16 QK/PV, fp32 accum + fp32 exp).
// Each CTA processes TWO 64-row q-tiles. Tile 0's P-normalize tail is
// interleaved into tile 1's mainloop (2 uint4 units/thread/iter), hiding
// its LDG/STG latency under mma. Only tile 1's tail runs exposed.
// 8 warps as two independent 128-thread groups (named barriers);
// group wn owns the 32-k blocks with (block index & 1) == wn.
// ---------------------------------------------------------------------------
static constexpr int RSB    = 272;                  // padded row stride (bytes)
static constexpr int OFF_Q  = 0;
static constexpr int QT     = 64 * RSB;             // 17408
static constexpr int OFF_ST = QT;                   // 17408
static constexpr int KSZ    = 32 * RSB;             // 8704 (32 k-rows)
static constexpr int S_KHI = 0, S_VHI = KSZ;
static constexpr int GSTAGE = 2 * KSZ;              // 17408 per stage (K+V)
static constexpr int GBUF   = 2 * GSTAGE;           // 34816 per group
static constexpr int OFF_INV = OFF_ST + 2 * GBUF;   // 87040
static constexpr int SMEM_BYTES = OFF_INV + 1024;   // 88064

__global__ __launch_bounds__(256, 2) void fused_attn_kernel(const float* __restrict__ Qf,
                                                            float* __restrict__ P,
                                                            float* __restrict__ R) {
    extern __shared__ char sm[];
    const uint32_t sb = smem_u32(sm);

    const int tid = threadIdx.x, lane = tid & 31, wid = tid >> 5;
    const int wm = wid & 3, wn = wid >> 2;
    const int gtid = tid & 127;
    const int g = lane >> 2, c2 = (lane & 3) * 2;
    const int b = blockIdx.y;
    const int qt0 = blockIdx.x * 128;

    const size_t kvbase = (size_t)b * LK * DIM;
    const uint32_t gbase = sb + OFF_ST + (uint32_t)(wn * GBUF);

    const uint32_t aoff  = (uint32_t)((lane & 15) * RSB + (lane >> 4) * 16);
    const uint32_t boff  = (uint32_t)(((lane & 7) + (lane >> 4) * 8) * RSB + ((lane >> 3) & 1) * 16);
    const uint32_t boffT = (uint32_t)(((lane & 7) + ((lane >> 3) & 1) * 8) * RSB + (lane >> 4) * 16);
    const uint32_t qaHi  = sb + OFF_Q + (uint32_t)(wm * 16) * RSB + aoff;

    float* partial = reinterpret_cast<float*>(sm + OFF_INV);
    float* inv     = reinterpret_cast<float*>(sm + OFF_INV + 256);

#pragma unroll
    for (int tile = 0; tile < 2; ++tile) {
        const int qt = qt0 + tile * 64;

        // ---- stage Q: load fp32, scale, convert, STS (all 256 threads) ----
        {
            const float* Qb = Qf + ((size_t)b * LQ + qt) * DIM;
#pragma unroll
            for (int it = 0; it < 8; ++it) {
                int i = tid + it * 256;                 // 0..2047 float4
                int row = i >> 5, col4 = (i & 31) * 4;
                float4 v = *reinterpret_cast<const float4*>(Qb + (size_t)row * DIM + col4);
                v.x *= SCALE_LOG2E; v.y *= SCALE_LOG2E; v.z *= SCALE_LOG2E; v.w *= SCALE_LOG2E;
                uint2 hh{packh2(__float2half_rn(v.x), __float2half_rn(v.y)),
                         packh2(__float2half_rn(v.z), __float2half_rn(v.w))};
                *reinterpret_cast<uint2*>(sm + OFF_Q + row * RSB + col4 * 2) = hh;
            }
        }
        // ---- stage chunk 0 for this group ----
        {
            const size_t kb = kvbase + (size_t)(wn * 32) * DIM;
#pragma unroll
            for (int it = 0; it < 4; ++it) {
                int i = gtid + it * 128;
                int row = i >> 4, chk = i & 15;
                uint32_t so = (uint32_t)(row * RSB + chk * 16);
                const size_t gg = kb + (size_t)row * DIM + chk * 8;
                cp16(gbase + S_KHI + so, g_Khi + gg);
                cp16(gbase + S_VHI + so, g_Vhi + gg);
            }
            cp_commit(); cp_wait0();
        }
        __syncthreads();   // Q visible + chunk 0 staged (and prev-tile smem reuse safe)

        float racc[16][4];
#pragma unroll
        for (int j = 0; j < 16; ++j)
#pragma unroll
            for (int c = 0; c < 4; ++c) racc[j][c] = 0.f;
        float rs0 = 0.f, rs1 = 0.f;

        __half* E0 = g_E + ((size_t)b * LQ + qt + wm * 16 + g) * LK + wn * 32 + c2;
        __half* E1 = E0 + (size_t)8 * LK;

        // tile0 tail sources (used when tile==1)
        const __half* Es0 = g_E + ((size_t)b * LQ + qt0) * LK;
        float* Pt0 = P + ((size_t)b * LQ + qt0) * LK;

#pragma unroll 1
        for (int kc = 0; kc < 32; ++kc) {
            // prefetch this group's next slice (k block 2*(kc+1)+wn)
            if (kc < 31) {
                const uint32_t dst = gbase + (uint32_t)(((kc + 1) & 1) * GSTAGE);
                const size_t kb = kvbase + (size_t)((kc + 1) * 64 + wn * 32) * DIM;
#pragma unroll
                for (int it = 0; it < 4; ++it) {
                    int i = gtid + it * 128;
                    int row = i >> 4, chk = i & 15;
                    uint32_t so = (uint32_t)(row * RSB + chk * 16);
                    const size_t gg = kb + (size_t)row * DIM + chk * 8;
                    cp16(dst + S_KHI + so, g_Khi + gg);
                    cp16(dst + S_VHI + so, g_Vhi + gg);
                }
                cp_commit();
            }

            const uint32_t buf = gbase + (uint32_t)((kc & 1) * GSTAGE);

            // ---- QK: warp computes S[16q x 32k], two 16-k halves ----
            float s0[2][4], s1[2][4];
#pragma unroll
            for (int j = 0; j < 2; ++j)
#pragma unroll
                for (int c = 0; c < 4; ++c) { s0[j][c] = 0.f; s1[j][c] = 0.f; }

            const uint32_t kh = buf + S_KHI + boff;
#pragma unroll
            for (int ks = 0; ks < 8; ++ks) {
                uint32_t qh[4], bh0[4], bh1[4];
                ldsm4(qh,  qaHi + ks * 32);
                ldsm4(bh0, kh + ks * 32);
                ldsm4(bh1, kh + 16 * RSB + ks * 32);
                mma16816(s0[0], qh, bh0[0], bh0[1]);
                mma16816(s0[1], qh, bh0[2], bh0[3]);
                mma16816(s1[0], qh, bh1[0], bh1[1]);
                mma16816(s1[1], qh, bh1[2], bh1[3]);
            }

            // ---- exp2, rowsums, pack fp16 A-frags ----
            float e0[2][4], e1[2][4];
#pragma unroll
            for (int j = 0; j < 2; ++j) {
                e0[j][0] = ex2(s0[j][0]); e0[j][1] = ex2(s0[j][1]);
                e0[j][2] = ex2(s0[j][2]); e0[j][3] = ex2(s0[j][3]);
                e1[j][0] = ex2(s1[j][0]); e1[j][1] = ex2(s1[j][1]);
                e1[j][2] = ex2(s1[j][2]); e1[j][3] = ex2(s1[j][3]);
                rs0 += e0[j][0] + e0[j][1] + e1[j][0] + e1[j][1];
                rs1 += e0[j][2] + e0[j][3] + e1[j][2] + e1[j][3];
            }
            uint32_t sh0[4], sh1[4];
#pragma unroll
            for (int j = 0; j < 2; ++j) {
                sh0[j * 2 + 0] = packh2(__float2half_rn(e0[j][0]), __float2half_rn(e0[j][1]));
                sh0[j * 2 + 1] = packh2(__float2half_rn(e0[j][2]), __float2half_rn(e0[j][3]));
                sh1[j * 2 + 0] = packh2(__float2half_rn(e1[j][0]), __float2half_rn(e1[j][1]));
                sh1[j * 2 + 1] = packh2(__float2half_rn(e1[j][2]), __float2half_rn(e1[j][3]));
            }

            // ---- store E fp16 (drains during PV) ----
            *reinterpret_cast<uint32_t*>(E0 + kc * 64)      = sh0[0];
            *reinterpret_cast<uint32_t*>(E1 + kc * 64)      = sh0[1];
            *reinterpret_cast<uint32_t*>(E0 + kc * 64 + 8)  = sh0[2];
            *reinterpret_cast<uint32_t*>(E1 + kc * 64 + 8)  = sh0[3];
            *reinterpret_cast<uint32_t*>(E0 + kc * 64 + 16) = sh1[0];
            *reinterpret_cast<uint32_t*>(E1 + kc * 64 + 16) = sh1[1];
            *reinterpret_cast<uint32_t*>(E0 + kc * 64 + 24) = sh1[2];
            *reinterpret_cast<uint32_t*>(E1 + kc * 64 + 24) = sh1[3];

            // ---- PV: racc += Sh0 * V(half0) + Sh1 * V(half1) ----
            const uint32_t vb = buf + S_VHI + boffT;
#pragma unroll
            for (int nb = 0; nb < 8; ++nb) {
                uint32_t bv[4];
                ldsm4t(bv, vb + nb * 32);
                mma16816(racc[nb * 2],     sh0, bv[0], bv[1]);
                mma16816(racc[nb * 2 + 1], sh0, bv[2], bv[3]);
            }
#pragma unroll
            for (int nb = 0; nb < 8; ++nb) {
                uint32_t bv[4];
                ldsm4t(bv, vb + 16 * RSB + nb * 32);
                mma16816(racc[nb * 2],     sh1, bv[0], bv[1]);
                mma16816(racc[nb * 2 + 1], sh1, bv[2], bv[3]);
            }

            // ---- interleaved tile0 tail (tile 1 only): 2 uint4 units/thread ----
            if (tile == 1) {
#pragma unroll
                for (int u = 0; u < 2; ++u) {
                    int idx = tid + (kc * 2 + u) * 256;   // 0..16383
                    int r = idx >> 8, c8 = idx & 255;
                    const uint4 hv = *reinterpret_cast<const uint4*>(Es0 + (size_t)r * LK + c8 * 8);
                    const float iv = inv[r];
                    const __half2* hp = reinterpret_cast<const __half2*>(&hv);
                    float2 f0 = __half22float2(hp[0]), f1 = __half22float2(hp[1]);
                    float2 f2 = __half22float2(hp[2]), f3 = __half22float2(hp[3]);
                    float4 o0{f0.x * iv, f0.y * iv, f1.x * iv, f1.y * iv};
                    float4 o1{f2.x * iv, f2.y * iv, f3.x * iv, f3.y * iv};
                    float* pd = Pt0 + (size_t)r * LK + c8 * 8;
                    *reinterpret_cast<float4*>(pd)     = o0;
                    *reinterpret_cast<float4*>(pd + 4) = o1;
                }
            }

            cp_wait0();
            barg(wn + 1);
        }

        // ---- cross-warp combine (wn pairs), rowsums, R store ----
        rs0 += __shfl_xor_sync(0xFFFFFFFFu, rs0, 1);
        rs0 += __shfl_xor_sync(0xFFFFFFFFu, rs0, 2);
        rs1 += __shfl_xor_sync(0xFFFFFFFFu, rs1, 1);
        rs1 += __shfl_xor_sync(0xFFFFFFFFu, rs1, 2);

        __syncthreads();   // mainloop (incl. interleaved tail inv reads) done

        if (wn == 1) {
            float4* red = reinterpret_cast<float4*>(sm + wm * 8192);
#pragma unroll
            for (int j = 0; j < 16; ++j)
                red[j * 32 + lane] = *reinterpret_cast<float4*>(racc[j]);
            if ((lane & 3) == 0) {
                partial[wm * 16 + g]     = rs0;
                partial[wm * 16 + 8 + g] = rs1;
            }
        }
        __syncthreads();

        if (wn == 0) {
            const float4* red = reinterpret_cast<const float4*>(sm + wm * 8192);
#pragma unroll
            for (int j = 0; j < 16; ++j) {
                float4 o = red[j * 32 + lane];
                racc[j][0] += o.x; racc[j][1] += o.y; racc[j][2] += o.z; racc[j][3] += o.w;
            }
            const int row0 = wm * 16 + g, row1 = row0 + 8;
            const float iv0 = 1.f / (rs0 + partial[row0]);
            const float iv1 = 1.f / (rs1 + partial[row1]);
            if ((lane & 3) == 0) { inv[row0] = iv0; inv[row1] = iv1; }

            float* Rp = R + ((size_t)b * LQ + qt + row0) * DIM + c2;
#pragma unroll
            for (int j = 0; j < 16; ++j) {
                float2 v0{racc[j][0] * iv0, racc[j][1] * iv0};
                float2 v1{racc[j][2] * iv1, racc[j][3] * iv1};
                *reinterpret_cast<float2*>(Rp + j * 8)           = v0;
                *reinterpret_cast<float2*>(Rp + 8 * DIM + j * 8) = v1;
            }
        }
        __syncthreads();   // inv[] now valid for this tile's tail
    }

    // ---- exposed tail: normalize tile 1's P (tile 0 was interleaved) ----
    const __half* Es = g_E + ((size_t)b * LQ + qt0 + 64) * LK;
    float* Pt = P + ((size_t)b * LQ + qt0 + 64) * LK;
#pragma unroll 4
    for (int it = 0; it < 64; ++it) {
        int idx = tid + it * 256;          // 0..16383 uint4 slots (8 halves each)
        int r = idx >> 8, c8 = idx & 255;
        const uint4 hv = *reinterpret_cast<const uint4*>(Es + (size_t)r * LK + c8 * 8);
        const float iv = inv[r];
        const __half2* hp = reinterpret_cast<const __half2*>(&hv);
        float2 f0 = __half22float2(hp[0]), f1 = __half22float2(hp[1]);
        float2 f2 = __half22float2(hp[2]), f3 = __half22float2(hp[3]);
        float4 o0{f0.x * iv, f0.y * iv, f1.x * iv, f1.y * iv};
        float4 o1{f2.x * iv, f2.y * iv, f3.x * iv, f3.y * iv};
        float* pd = Pt + (size_t)r * LK + c8 * 8;
        *reinterpret_cast<float4*>(pd)     = o0;
        *reinterpret_cast<float4*>(pd + 4) = o1;
    }
}

// ---------------------------------------------------------------------------
// Launch: d_out = [ R | P ]
// ---------------------------------------------------------------------------
extern "C" void kernel_launch(void* const* d_in, const int* in_sizes, int n_in,
                              void* d_out, int out_size) {
    const float* Q = (const float*)d_in[0];
    const float* K = (const float*)d_in[1];
    const float* V = (const float*)d_in[2];
    float* R = (float*)d_out;
    float* P = (float*)d_out + (size_t)BATCH * LQ * DIM;

    cudaFuncSetAttribute(fused_attn_kernel, cudaFuncAttributeMaxDynamicSharedMemorySize, SMEM_BYTES);

    {
        dim3 grid((unsigned)(NEL / 4 / 256), 2);
        preconvert_kernel<<<grid, 256>>>(K, V);
    }
    {
        dim3 grid(LQ / 128, BATCH);
        fused_attn_kernel<<<grid, 256, SMEM_BYTES>>>(Q, P, R);
    }
}